// round 13
// baseline (speedup 1.0000x reference)
#include <cuda_runtime.h>
#include <cuda_fp16.h>
#include <cstdint>

// ---------------------------------------------------------------------------
// Problem constants
// ---------------------------------------------------------------------------
#define NB      256
#define NT      81
#define WIN     1022
#define NF      69
#define M1      (NB*NT)      // 20736 = 162*128
#define M2      (NB*NF)      // 17664 = 138*128
#define OUTJ    28550
#define XBSTR   82944        // 512*81*2
#define OBSTR   70656        // 512*69*2
#define OKSTR   138          // 69*2

#define KC      32           // K per chunk
#define CH      32           // 1024/32 chunks
#define TM      128
#define TN      128
#define STAGES  4

// smem per stage (bytes): A[128][40] fp16 = 10240 ; B[32][136] fp16 = 8704
#define A_STRIDE    40       // halfs (80 B row; conflict-free for ldsm)
#define B_STRIDEB   272      // bytes (136 halfs)
#define A_OFF       0
#define B_OFF       10240
#define STAGE_BYTES 18944
#define SMEM_DYN    (STAGES*STAGE_BYTES)   // 75776 (x2 CTAs = 151552 < 228KB)
// epilogue reuse: fp32 tile 128 x 130 = 66560 B <= 75776 ; half tile 128x136 = 34816 B

// ---------------------------------------------------------------------------
// Device-global scratch
// ---------------------------------------------------------------------------
__device__ float  g_synwin[1024];
__device__ __half g_binv_h[1024*1024];   // [k=2f+c][n]   (B of GEMM1)
__device__ __half g_bfwd_h[1024*1024];   // [k=n][m=2f+c] (B of GEMM2)
__device__ __half g_xhi[(size_t)M1*1024];
__device__ __half g_tf [(size_t)M1*1024];   // iSTFT frames (fp16)
__device__ __half g_fhi[(size_t)M2*1024];   // STFT input frames (fp16)

// ---------------------------------------------------------------------------
// PTX helpers (baseline ISA: ldmatrix + mma.sync + cp.async, sm_80+)
// ---------------------------------------------------------------------------
__device__ __forceinline__ uint32_t smem_to_u32(const void* p) {
    uint32_t a;
    asm("{ .reg .u64 t; cvta.to.shared.u64 t, %1; cvt.u32.u64 %0, t; }"
        : "=r"(a) : "l"(p));
    return a;
}
__device__ __forceinline__ void ldsm_x4(uint32_t* r, uint32_t addr) {
    asm volatile("ldmatrix.sync.aligned.m8n8.x4.shared.b16 {%0,%1,%2,%3}, [%4];"
        : "=r"(r[0]), "=r"(r[1]), "=r"(r[2]), "=r"(r[3]) : "r"(addr));
}
__device__ __forceinline__ void ldsm_x4_t(uint32_t* r, uint32_t addr) {
    asm volatile("ldmatrix.sync.aligned.m8n8.x4.trans.shared.b16 {%0,%1,%2,%3}, [%4];"
        : "=r"(r[0]), "=r"(r[1]), "=r"(r[2]), "=r"(r[3]) : "r"(addr));
}
__device__ __forceinline__ void mma16816(float* d, const uint32_t* a, const uint32_t* b) {
    asm volatile(
        "mma.sync.aligned.m16n8k16.row.col.f32.f16.f16.f32 "
        "{%0,%1,%2,%3}, {%4,%5,%6,%7}, {%8,%9}, {%0,%1,%2,%3};"
        : "+f"(d[0]), "+f"(d[1]), "+f"(d[2]), "+f"(d[3])
        : "r"(a[0]), "r"(a[1]), "r"(a[2]), "r"(a[3]), "r"(b[0]), "r"(b[1]));
}
__device__ __forceinline__ void cp16(uint32_t saddr, const void* gaddr) {
    asm volatile("cp.async.cg.shared.global [%0], [%1], 16;"
        :: "r"(saddr), "l"(gaddr));
}
#define CP_COMMIT() asm volatile("cp.async.commit_group;" ::: "memory")
#define CP_WAIT(N)  asm volatile("cp.async.wait_group %0;" :: "n"(N) : "memory")

// ---------------------------------------------------------------------------
// Prep kernels
// ---------------------------------------------------------------------------
__global__ void fill_synwin_kernel() {
    int n = threadIdx.x;
    float val = 0.f;
    if (n < WIN) {
        const float c = 6.283185307179586477f / (float)WIN;
        float w = 0.5f - 0.5f * cosf(c * (float)n);
        int d = n % 400;
        float denom = 0.f;
        #pragma unroll
        for (int j = 0; j < 3; ++j) {
            int idx = d + 400 * j;
            if (idx < WIN) {
                float wj = 0.5f - 0.5f * cosf(c * (float)idx);
                denom += wj * wj;
            }
        }
        val = w / denom;
    }
    g_synwin[n] = val;
}

// g_binv[k=2f+c][n] = synwin[n]/WIN * w_f * {cos,-sin}(2*pi*f*n/WIN); 0 for n>=1022
__global__ void fill_binv_kernel() {
    int idx = blockIdx.x * blockDim.x + threadIdx.x;   // 512*1024
    int f = idx >> 10;
    int n = idx & 1023;
    float re = 0.f, im = 0.f;
    if (n < WIN) {
        unsigned m = (unsigned)(f * n) % (unsigned)WIN;
        float ang = 6.283185307179586477f * (float)m / (float)WIN;
        float s, c;
        __sincosf(ang, &s, &c);
        float wk = (f == 0 || f == 511) ? 1.f : 2.f;
        float scale = wk * g_synwin[n] * (1.0f / (float)WIN);
        re = scale * c;
        im = -scale * s;
    }
    g_binv_h[(size_t)(2*f) * 1024 + n]   = __float2half_rn(re);
    g_binv_h[(size_t)(2*f+1) * 1024 + n] = __float2half_rn(im);
}

// g_bfwd[k=n][m=2f+c] = hann[n] * {cos,-sin}(2*pi*f*n/WIN); zero rows n>=1022
__global__ void fill_bfwd_kernel() {
    int idx = blockIdx.x * blockDim.x + threadIdx.x;   // 1024*512
    int n = idx >> 9;
    int f = idx & 511;
    float re = 0.f, im = 0.f;
    if (n < WIN) {
        const float cc = 6.283185307179586477f / (float)WIN;
        unsigned m = (unsigned)(f * n) % (unsigned)WIN;
        float ang = cc * (float)m;
        float s, c;
        __sincosf(ang, &s, &c);
        float h = 0.5f - 0.5f * __cosf(cc * (float)n);
        re = h * c;
        im = -h * s;
    }
    g_bfwd_h[(size_t)n * 1024 + 2*f]   = __float2half_rn(re);
    g_bfwd_h[(size_t)n * 1024 + 2*f+1] = __float2half_rn(im);
}

// x (B,F,T,2) -> g_xhi [(b,t)][2f+c]  -- smem tile transpose
__global__ void __launch_bounds__(256) convert_x_kernel(const float* __restrict__ x) {
    __shared__ __half2 tile[64 * 81];
    const int b  = blockIdx.y;
    const int f0 = blockIdx.x * 64;
    const float* xb = x + (size_t)b * XBSTR;
    for (int i = threadIdx.x; i < 64 * 81; i += 256) {
        int fi = i / 81, t = i - fi * 81;
        float2 v = *(const float2*)(xb + (size_t)(f0 + fi) * 162 + t * 2);
        tile[fi * 81 + t] = __floats2half2_rn(v.x, v.y);
    }
    __syncthreads();
    for (int i = threadIdx.x; i < 64 * 81; i += 256) {
        int t = i >> 6, fi = i & 63;
        *(__half2*)(g_xhi + (size_t)(b * 81 + t) * 1024 + 2 * (f0 + fi)) = tile[fi * 81 + t];
    }
}

// ---------------------------------------------------------------------------
// Fold (fused): overlap-add + crossfade + scatter into STFT frame rows (fp16)
// ---------------------------------------------------------------------------
__device__ __forceinline__ float sigval(const __half* __restrict__ tfb, int s) {
    int t1 = s / 400; if (t1 > 80) t1 = 80;
    int t0 = (s >= WIN) ? (s - (WIN - 400)) / 400 : 0;
    float v = 0.f;
    for (int t = t0; t <= t1; ++t)
        v += __half2float(tfb[t * 1024 + (s - 400 * t)]);
    return v;
}

__global__ void fold_kernel() {
    int j = blockIdx.x * blockDim.x + threadIdx.x;
    int b = blockIdx.y;
    if (j >= OUTJ) return;
    int k, r;
    if (j < 1000) { k = 0; r = j; }
    else {
        int q  = (j - 1000) / 950;
        int rr = (j - 1000) - q * 950;
        k = q + 1;
        r = 50 + rr;
    }
    float cc = 1.f, dec = 0.f, inc = 0.f;
    bool xfade = (r >= 950) && (k <= 28);
    if (xfade) {
        cc  = 0.f;
        dec = (float)(1000 - r) * 0.02f;
        inc = (float)(r - 949) * 0.02f;
    }
    const __half* tfb = g_tf + (size_t)b * NT * 1024;
    float o = (cc + dec) * sigval(tfb, k * 1100 + r);
    if (xfade)
        o += inc * sigval(tfb, (k + 1) * 1100 + (r - 950));

    int fmax = j / 400; if (fmax > NF - 1) fmax = NF - 1;
    int fmin = (j >= WIN) ? (j - WIN) / 400 + 1 : 0;
    __half hv = __float2half_rn(o);
    __half* fb = g_fhi + (size_t)b * NF * 1024;
    for (int f = fmin; f <= fmax; ++f)
        fb[f * 1024 + (j - 400 * f)] = hv;
}

// zero the 2-column padding of g_fhi (n = 1022, 1023)
__global__ void pad_frames_kernel() {
    int idx = blockIdx.x * blockDim.x + threadIdx.x;
    if (idx >= M2) return;
    *(__half2*)(g_fhi + (size_t)idx * 1024 + WIN) = __half2{};
}

// ---------------------------------------------------------------------------
// fp16 tensor-core GEMM, 128x128 CTA tile, KC=32, cp.async 4-stage pipeline,
// 2 CTAs/SM. 8 warps as 2(M)x4(N); single product A*B.
// Coalesced epilogues via smem staging (reuses pipeline smem).
// MODE 0: A=g_xhi, B=g_binv_h -> g_tf (fp16)
// MODE 1: A=g_fhi, B=g_bfwd_h -> out (fp32)
// ---------------------------------------------------------------------------
template <int MODE>
__global__ void __launch_bounds__(256, 2) gemm_mma_kernel(float* __restrict__ outp) {
    extern __shared__ char smem[];
    const uint32_t sbase = smem_to_u32(smem);
    const int tid  = threadIdx.x;
    const int wid  = tid >> 5;
    const int lane = tid & 31;
    const int wm   = wid & 1;        // 2 warp rows (64 each)
    const int wn   = wid >> 1;       // 4 warp cols (32 each)
    const int n0   = blockIdx.x * TN;
    const int row0 = blockIdx.y * TM;

    const __half* Ah = (MODE == 0) ? g_xhi    : g_fhi;
    const __half* Bh = (MODE == 0) ? g_binv_h : g_bfwd_h;

    float acc[4][4][4];
    #pragma unroll
    for (int i = 0; i < 4; ++i)
        #pragma unroll
        for (int j = 0; j < 4; ++j)
            #pragma unroll
            for (int q = 0; q < 4; ++q) acc[i][j][q] = 0.f;

    const int a_row = tid >> 2, a_seg = tid & 3;
    const int b_row = tid >> 4, b_seg = tid & 15;

    auto load_chunk = [&](int c, int buf) {
        const size_t kt = (size_t)c * KC;
        const uint32_t sa = sbase + buf * STAGE_BYTES;
        #pragma unroll
        for (int i = 0; i < 2; ++i) {
            int row = a_row + i * 64;
            cp16(sa + A_OFF + row * (A_STRIDE*2) + a_seg * 16,
                 Ah + (size_t)(row0 + row) * 1024 + kt + a_seg * 8);
        }
        #pragma unroll
        for (int i = 0; i < 2; ++i) {
            int row = b_row + i * 16;
            cp16(sa + B_OFF + row * B_STRIDEB + b_seg * 16,
                 Bh + (size_t)(kt + row) * 1024 + n0 + b_seg * 8);
        }
    };

    const uint32_t lrow = lane & 15;
    const uint32_t lsel = lane >> 4;

    #pragma unroll
    for (int s = 0; s < STAGES - 1; ++s) {
        load_chunk(s, s);
        CP_COMMIT();
    }

    for (int c = 0; c < CH; ++c) {
        CP_WAIT(STAGES - 2);
        __syncthreads();

        if (c + STAGES - 1 < CH)
            load_chunk(c + STAGES - 1, (c + STAGES - 1) % STAGES);
        CP_COMMIT();

        const int buf = c % STAGES;
        const uint32_t sb = sbase + buf * STAGE_BYTES;
        const uint32_t aB = sb + A_OFF + (wm * 64 + lrow) * (A_STRIDE*2) + lsel * 16;
        const uint32_t bB = sb + B_OFF + lrow * B_STRIDEB + (wn * 32 + lsel * 8) * 2;

        #pragma unroll
        for (int ks = 0; ks < 2; ++ks) {
            uint32_t a[4][4];
            #pragma unroll
            for (int mt = 0; mt < 4; ++mt)
                ldsm_x4(a[mt], aB + mt * 16 * (A_STRIDE*2) + ks * 32);
            uint32_t b[2][4];
            const uint32_t pb = bB + ks * 16 * B_STRIDEB;
            #pragma unroll
            for (int bt = 0; bt < 2; ++bt)
                ldsm_x4_t(b[bt], pb + bt * 32);
            #pragma unroll
            for (int mt = 0; mt < 4; ++mt)
                #pragma unroll
                for (int nt = 0; nt < 4; ++nt)
                    mma16816(acc[mt][nt], a[mt], &b[nt >> 1][(nt & 1) * 2]);
        }
    }

    // ---- epilogue: stage to smem, then coalesced global stores ----
    __syncthreads();   // all warps done reading pipeline smem

    if (MODE == 0) {
        __half* tileh = (__half*)smem;                // [128][136] halfs
        #pragma unroll
        for (int mt = 0; mt < 4; ++mt) {
            #pragma unroll
            for (int half = 0; half < 2; ++half) {
                const int r = wm * 64 + mt * 16 + (lane >> 2) + half * 8;
                #pragma unroll
                for (int nt = 0; nt < 4; ++nt) {
                    const int col = wn * 32 + nt * 8 + (lane & 3) * 2;
                    *(__half2*)(tileh + r * 136 + col) =
                        __floats2half2_rn(acc[mt][nt][half * 2], acc[mt][nt][half * 2 + 1]);
                }
            }
        }
        __syncthreads();
        // 128 rows x 16 uint4 each, coalesced
        #pragma unroll
        for (int u = tid; u < 128 * 16; u += 256) {
            int r = u >> 4, s = u & 15;
            *(uint4*)(g_tf + (size_t)(row0 + r) * 1024 + n0 + s * 8) =
                *(const uint4*)(tileh + r * 136 + s * 8);
        }
    } else {
        float* tilef = (float*)smem;                  // [128][130] floats
        #pragma unroll
        for (int mt = 0; mt < 4; ++mt) {
            #pragma unroll
            for (int half = 0; half < 2; ++half) {
                const int r = wm * 64 + mt * 16 + (lane >> 2) + half * 8;
                #pragma unroll
                for (int nt = 0; nt < 4; ++nt) {
                    const int col = wn * 32 + nt * 8 + (lane & 3) * 2;
                    tilef[r * 130 + col]     = acc[mt][nt][half * 2];
                    tilef[r * 130 + col + 1] = acc[mt][nt][half * 2 + 1];
                }
            }
        }
        __syncthreads();
        // output: out[b*OBSTR + k*138 + f*2 + c] ; order (k16, j=(r,c)) -> coalesced
        const int k0 = n0 >> 1;
        #pragma unroll 4
        for (int i = tid; i < 128 * 128; i += 256) {
            int k16 = i >> 8, j = i & 255;
            int r = j >> 1, c = j & 1;
            int gr = row0 + r;
            int b = gr / NF, f = gr - b * NF;
            outp[(size_t)b * OBSTR + (k0 + k16) * OKSTR + f * 2 + c] =
                tilef[r * 130 + k16 * 2 + c];
        }
    }
}

// ---------------------------------------------------------------------------
// Launch (ordered so the profiled launch #4 = gemm<0>)
// ---------------------------------------------------------------------------
extern "C" void kernel_launch(void* const* d_in, const int* in_sizes, int n_in,
                              void* d_out, int out_size) {
    const float* x = (const float*)d_in[0];
    float* out = (float*)d_out;

    cudaFuncSetAttribute((const void*)gemm_mma_kernel<0>,
                         cudaFuncAttributeMaxDynamicSharedMemorySize, SMEM_DYN);
    cudaFuncSetAttribute((const void*)gemm_mma_kernel<1>,
                         cudaFuncAttributeMaxDynamicSharedMemorySize, SMEM_DYN);

    convert_x_kernel<<<dim3(8, NB), 256>>>(x);
    fill_synwin_kernel<<<1, 1024>>>();
    fill_binv_kernel<<<2048, 256>>>();

    gemm_mma_kernel<0><<<dim3(8, 162), 256, SMEM_DYN>>>(nullptr);

    fill_bfwd_kernel<<<2048, 256>>>();
    pad_frames_kernel<<<(M2 + 255) / 256, 256>>>();
    fold_kernel<<<dim3((OUTJ + 255) / 256, NB), 256>>>();

    gemm_mma_kernel<1><<<dim3(8, 138), 256, SMEM_DYN>>>(out);
}

// round 14
// speedup vs baseline: 1.0617x; 1.0617x over previous
#include <cuda_runtime.h>
#include <cuda_fp16.h>
#include <cstdint>

// ---------------------------------------------------------------------------
// Problem constants
// ---------------------------------------------------------------------------
#define NB      256
#define NT      81
#define WIN     1022
#define NF      69
#define M1      (NB*NT)      // 20736 = 162*128
#define M2      (NB*NF)      // 17664 = 138*128
#define OUTJ    28550
#define XBSTR   82944        // 512*81*2
#define OBSTR   70656        // 512*69*2
#define OKSTR   138          // 69*2

#define KC      64           // K per chunk
#define CH      16           // 1024/64 chunks
#define TM      128
#define TN      128
#define STAGES  3

// smem per stage (bytes): A[128][72] fp16 = 18432 ; B[64][136] fp16 = 17408
#define A_STRIDEB   144      // bytes per A row (144/16=9 odd -> ldsm conflict-free)
#define B_STRIDEB   272      // bytes per B row (272/16=17 odd -> conflict-free)
#define A_OFF       0
#define B_OFF       18432
#define STAGE_BYTES 35840
#define SMEM_DYN    (STAGES*STAGE_BYTES)   // 107520 (x2 CTAs = 215040 < 228KB)
// epilogue reuse: fp32 tile 128x130x4 = 66560 <= 107520 ; half tile 128x136x2 = 34816

// ---------------------------------------------------------------------------
// Device-global scratch
// ---------------------------------------------------------------------------
__device__ __half g_binv_h[1024*1024];   // [k=2f+c][n]   (B of GEMM1)
__device__ __half g_bfwd_h[1024*1024];   // [k=n][m=2f+c] (B of GEMM2)
__device__ __half g_xhi[(size_t)M1*1024];
__device__ __half g_tf [(size_t)M1*1024];   // iSTFT frames (fp16)
__device__ __half g_fhi[(size_t)M2*1024];   // STFT input frames (fp16)

// ---------------------------------------------------------------------------
// PTX helpers (baseline ISA: ldmatrix + mma.sync + cp.async, sm_80+)
// ---------------------------------------------------------------------------
__device__ __forceinline__ uint32_t smem_to_u32(const void* p) {
    uint32_t a;
    asm("{ .reg .u64 t; cvta.to.shared.u64 t, %1; cvt.u32.u64 %0, t; }"
        : "=r"(a) : "l"(p));
    return a;
}
__device__ __forceinline__ void ldsm_x4(uint32_t* r, uint32_t addr) {
    asm volatile("ldmatrix.sync.aligned.m8n8.x4.shared.b16 {%0,%1,%2,%3}, [%4];"
        : "=r"(r[0]), "=r"(r[1]), "=r"(r[2]), "=r"(r[3]) : "r"(addr));
}
__device__ __forceinline__ void ldsm_x4_t(uint32_t* r, uint32_t addr) {
    asm volatile("ldmatrix.sync.aligned.m8n8.x4.trans.shared.b16 {%0,%1,%2,%3}, [%4];"
        : "=r"(r[0]), "=r"(r[1]), "=r"(r[2]), "=r"(r[3]) : "r"(addr));
}
__device__ __forceinline__ void mma16816(float* d, const uint32_t* a, const uint32_t* b) {
    asm volatile(
        "mma.sync.aligned.m16n8k16.row.col.f32.f16.f16.f32 "
        "{%0,%1,%2,%3}, {%4,%5,%6,%7}, {%8,%9}, {%0,%1,%2,%3};"
        : "+f"(d[0]), "+f"(d[1]), "+f"(d[2]), "+f"(d[3])
        : "r"(a[0]), "r"(a[1]), "r"(a[2]), "r"(a[3]), "r"(b[0]), "r"(b[1]));
}
__device__ __forceinline__ void cp16(uint32_t saddr, const void* gaddr) {
    asm volatile("cp.async.cg.shared.global [%0], [%1], 16;"
        :: "r"(saddr), "l"(gaddr));
}
#define CP_COMMIT() asm volatile("cp.async.commit_group;" ::: "memory")
#define CP_WAIT(N)  asm volatile("cp.async.wait_group %0;" :: "n"(N) : "memory")

// ---------------------------------------------------------------------------
// Prep kernels
// ---------------------------------------------------------------------------
// synthesis window value (inline, fast math)
__device__ __forceinline__ float synwin_val(int n) {
    const float c = 6.283185307179586477f / (float)WIN;
    float w = 0.5f - 0.5f * __cosf(c * (float)n);
    int d = n % 400;
    float denom = 0.f;
    #pragma unroll
    for (int j = 0; j < 3; ++j) {
        int idx = d + 400 * j;
        if (idx < WIN) {
            float wj = 0.5f - 0.5f * __cosf(c * (float)idx);
            denom += wj * wj;
        }
    }
    return w / denom;
}

// g_binv[k=2f+c][n] = synwin[n]/WIN * w_f * {cos,-sin}(2*pi*f*n/WIN); 0 for n>=1022
__global__ void fill_binv_kernel() {
    int idx = blockIdx.x * blockDim.x + threadIdx.x;   // 512*1024
    int f = idx >> 10;
    int n = idx & 1023;
    float re = 0.f, im = 0.f;
    if (n < WIN) {
        unsigned m = (unsigned)(f * n) % (unsigned)WIN;
        float ang = 6.283185307179586477f * (float)m / (float)WIN;
        float s, c;
        __sincosf(ang, &s, &c);
        float wk = (f == 0 || f == 511) ? 1.f : 2.f;
        float scale = wk * synwin_val(n) * (1.0f / (float)WIN);
        re = scale * c;
        im = -scale * s;
    }
    g_binv_h[(size_t)(2*f) * 1024 + n]   = __float2half_rn(re);
    g_binv_h[(size_t)(2*f+1) * 1024 + n] = __float2half_rn(im);
}

// g_bfwd[k=n][m=2f+c] = hann[n] * {cos,-sin}(2*pi*f*n/WIN); zero rows n>=1022
__global__ void fill_bfwd_kernel() {
    int idx = blockIdx.x * blockDim.x + threadIdx.x;   // 1024*512
    int n = idx >> 9;
    int f = idx & 511;
    float re = 0.f, im = 0.f;
    if (n < WIN) {
        const float cc = 6.283185307179586477f / (float)WIN;
        unsigned m = (unsigned)(f * n) % (unsigned)WIN;
        float ang = cc * (float)m;
        float s, c;
        __sincosf(ang, &s, &c);
        float h = 0.5f - 0.5f * __cosf(cc * (float)n);
        re = h * c;
        im = -h * s;
    }
    g_bfwd_h[(size_t)n * 1024 + 2*f]   = __float2half_rn(re);
    g_bfwd_h[(size_t)n * 1024 + 2*f+1] = __float2half_rn(im);
}

// x (B,F,T,2) -> g_xhi [(b,t)][2f+c]  -- smem tile transpose
__global__ void __launch_bounds__(256) convert_x_kernel(const float* __restrict__ x) {
    __shared__ __half2 tile[64 * 81];
    const int b  = blockIdx.y;
    const int f0 = blockIdx.x * 64;
    const float* xb = x + (size_t)b * XBSTR;
    for (int i = threadIdx.x; i < 64 * 81; i += 256) {
        int fi = i / 81, t = i - fi * 81;
        float2 v = *(const float2*)(xb + (size_t)(f0 + fi) * 162 + t * 2);
        tile[fi * 81 + t] = __floats2half2_rn(v.x, v.y);
    }
    __syncthreads();
    for (int i = threadIdx.x; i < 64 * 81; i += 256) {
        int t = i >> 6, fi = i & 63;
        *(__half2*)(g_xhi + (size_t)(b * 81 + t) * 1024 + 2 * (f0 + fi)) = tile[fi * 81 + t];
    }
}

// ---------------------------------------------------------------------------
// Fold (fused): overlap-add + crossfade + scatter into STFT frame rows (fp16)
// Also zeroes the 2-column frame padding (j in [OUTJ, OUTJ+NF)).
// ---------------------------------------------------------------------------
__device__ __forceinline__ float sigval(const __half* __restrict__ tfb, int s) {
    int t1 = s / 400; if (t1 > 80) t1 = 80;
    int t0 = (s >= WIN) ? (s - (WIN - 400)) / 400 : 0;
    float v = 0.f;
    for (int t = t0; t <= t1; ++t)
        v += __half2float(tfb[t * 1024 + (s - 400 * t)]);
    return v;
}

__global__ void fold_kernel() {
    int j = blockIdx.x * blockDim.x + threadIdx.x;
    int b = blockIdx.y;
    __half* fb = g_fhi + (size_t)b * NF * 1024;
    if (j >= OUTJ) {
        int f = j - OUTJ;
        if (f < NF)
            *(__half2*)(fb + f * 1024 + WIN) = __half2{};
        return;
    }
    int k, r;
    if (j < 1000) { k = 0; r = j; }
    else {
        int q  = (j - 1000) / 950;
        int rr = (j - 1000) - q * 950;
        k = q + 1;
        r = 50 + rr;
    }
    float cc = 1.f, dec = 0.f, inc = 0.f;
    bool xfade = (r >= 950) && (k <= 28);
    if (xfade) {
        cc  = 0.f;
        dec = (float)(1000 - r) * 0.02f;
        inc = (float)(r - 949) * 0.02f;
    }
    const __half* tfb = g_tf + (size_t)b * NT * 1024;
    float o = (cc + dec) * sigval(tfb, k * 1100 + r);
    if (xfade)
        o += inc * sigval(tfb, (k + 1) * 1100 + (r - 950));

    int fmax = j / 400; if (fmax > NF - 1) fmax = NF - 1;
    int fmin = (j >= WIN) ? (j - WIN) / 400 + 1 : 0;
    __half hv = __float2half_rn(o);
    for (int f = fmin; f <= fmax; ++f)
        fb[f * 1024 + (j - 400 * f)] = hv;
}

// ---------------------------------------------------------------------------
// fp16 tensor-core GEMM, 128x128 CTA tile, KC=64, cp.async 3-stage pipeline,
// 2 CTAs/SM. 8 warps as 2(M)x4(N); single product A*B.
// Fully-coalesced loaders: each warp streams 4x128B A rows / 2x256B B rows.
// Coalesced epilogues via smem staging (reuses pipeline smem).
// MODE 0: A=g_xhi, B=g_binv_h -> g_tf (fp16)
// MODE 1: A=g_fhi, B=g_bfwd_h -> out (fp32)
// ---------------------------------------------------------------------------
template <int MODE>
__global__ void __launch_bounds__(256, 2) gemm_mma_kernel(float* __restrict__ outp) {
    extern __shared__ char smem[];
    const uint32_t sbase = smem_to_u32(smem);
    const int tid  = threadIdx.x;
    const int wid  = tid >> 5;
    const int lane = tid & 31;
    const int wm   = wid & 1;        // 2 warp rows (64 each)
    const int wn   = wid >> 1;       // 4 warp cols (32 each)
    const int n0   = blockIdx.x * TN;
    const int row0 = blockIdx.y * TM;

    const __half* Ah = (MODE == 0) ? g_xhi    : g_fhi;
    const __half* Bh = (MODE == 0) ? g_binv_h : g_bfwd_h;

    float acc[4][4][4];
    #pragma unroll
    for (int i = 0; i < 4; ++i)
        #pragma unroll
        for (int j = 0; j < 4; ++j)
            #pragma unroll
            for (int q = 0; q < 4; ++q) acc[i][j][q] = 0.f;

    auto load_chunk = [&](int c, int buf) {
        const size_t kt = (size_t)c * KC;
        const uint32_t sa = sbase + buf * STAGE_BYTES;
        // A: 128 rows x 8 segs of 16B; warp covers 4 full 128B rows per iter
        #pragma unroll
        for (int i = 0; i < 4; ++i) {
            int unit = tid + 256 * i;
            int row = unit >> 3, seg = unit & 7;
            cp16(sa + A_OFF + row * A_STRIDEB + seg * 16,
                 Ah + (size_t)(row0 + row) * 1024 + kt + seg * 8);
        }
        // B: 64 rows x 16 segs of 16B; warp covers 2 full 256B rows per iter
        #pragma unroll
        for (int i = 0; i < 4; ++i) {
            int unit = tid + 256 * i;
            int row = unit >> 4, seg = unit & 15;
            cp16(sa + B_OFF + row * B_STRIDEB + seg * 16,
                 Bh + (size_t)(kt + row) * 1024 + n0 + seg * 8);
        }
    };

    const uint32_t lrow = lane & 15;
    const uint32_t lsel = lane >> 4;

    #pragma unroll
    for (int s = 0; s < STAGES - 1; ++s) {
        load_chunk(s, s);
        CP_COMMIT();
    }

    for (int c = 0; c < CH; ++c) {
        CP_WAIT(STAGES - 2);
        __syncthreads();

        if (c + STAGES - 1 < CH)
            load_chunk(c + STAGES - 1, (c + STAGES - 1) % STAGES);
        CP_COMMIT();

        const int buf = c % STAGES;
        const uint32_t sb = sbase + buf * STAGE_BYTES;
        const uint32_t aB = sb + A_OFF + (wm * 64 + lrow) * A_STRIDEB + lsel * 16;
        const uint32_t bB = sb + B_OFF + lrow * B_STRIDEB + (wn * 32 + lsel * 8) * 2;

        #pragma unroll
        for (int ks = 0; ks < 4; ++ks) {
            uint32_t a[4][4];
            #pragma unroll
            for (int mt = 0; mt < 4; ++mt)
                ldsm_x4(a[mt], aB + mt * 16 * A_STRIDEB + ks * 32);
            uint32_t b[2][4];
            const uint32_t pb = bB + ks * 16 * B_STRIDEB;
            #pragma unroll
            for (int bt = 0; bt < 2; ++bt)
                ldsm_x4_t(b[bt], pb + bt * 32);
            #pragma unroll
            for (int mt = 0; mt < 4; ++mt)
                #pragma unroll
                for (int nt = 0; nt < 4; ++nt)
                    mma16816(acc[mt][nt], a[mt], &b[nt >> 1][(nt & 1) * 2]);
        }
    }

    // ---- epilogue: stage to smem, then coalesced global stores ----
    __syncthreads();   // all warps done reading pipeline smem

    if (MODE == 0) {
        __half* tileh = (__half*)smem;                // [128][136] halfs
        #pragma unroll
        for (int mt = 0; mt < 4; ++mt) {
            #pragma unroll
            for (int half = 0; half < 2; ++half) {
                const int r = wm * 64 + mt * 16 + (lane >> 2) + half * 8;
                #pragma unroll
                for (int nt = 0; nt < 4; ++nt) {
                    const int col = wn * 32 + nt * 8 + (lane & 3) * 2;
                    *(__half2*)(tileh + r * 136 + col) =
                        __floats2half2_rn(acc[mt][nt][half * 2], acc[mt][nt][half * 2 + 1]);
                }
            }
        }
        __syncthreads();
        #pragma unroll
        for (int u = tid; u < 128 * 16; u += 256) {
            int r = u >> 4, s = u & 15;
            *(uint4*)(g_tf + (size_t)(row0 + r) * 1024 + n0 + s * 8) =
                *(const uint4*)(tileh + r * 136 + s * 8);
        }
    } else {
        float* tilef = (float*)smem;                  // [128][130] floats
        #pragma unroll
        for (int mt = 0; mt < 4; ++mt) {
            #pragma unroll
            for (int half = 0; half < 2; ++half) {
                const int r = wm * 64 + mt * 16 + (lane >> 2) + half * 8;
                #pragma unroll
                for (int nt = 0; nt < 4; ++nt) {
                    const int col = wn * 32 + nt * 8 + (lane & 3) * 2;
                    tilef[r * 130 + col]     = acc[mt][nt][half * 2];
                    tilef[r * 130 + col + 1] = acc[mt][nt][half * 2 + 1];
                }
            }
        }
        __syncthreads();
        const int k0 = n0 >> 1;
        #pragma unroll 4
        for (int i = tid; i < 128 * 128; i += 256) {
            int k16 = i >> 8, j = i & 255;
            int r = j >> 1, c = j & 1;
            int gr = row0 + r;
            int b = gr / NF, f = gr - b * NF;
            outp[(size_t)b * OBSTR + (k0 + k16) * OKSTR + f * 2 + c] =
                tilef[r * 130 + k16 * 2 + c];
        }
    }
}

// ---------------------------------------------------------------------------
// Launch (6 launches; ncu slot lands on gemm<1> for fresh visibility)
// ---------------------------------------------------------------------------
extern "C" void kernel_launch(void* const* d_in, const int* in_sizes, int n_in,
                              void* d_out, int out_size) {
    const float* x = (const float*)d_in[0];
    float* out = (float*)d_out;

    cudaFuncSetAttribute((const void*)gemm_mma_kernel<0>,
                         cudaFuncAttributeMaxDynamicSharedMemorySize, SMEM_DYN);
    cudaFuncSetAttribute((const void*)gemm_mma_kernel<1>,
                         cudaFuncAttributeMaxDynamicSharedMemorySize, SMEM_DYN);

    convert_x_kernel<<<dim3(8, NB), 256>>>(x);
    fill_binv_kernel<<<2048, 256>>>();

    gemm_mma_kernel<0><<<dim3(8, 162), 256, SMEM_DYN>>>(nullptr);

    fill_bfwd_kernel<<<2048, 256>>>();
    fold_kernel<<<dim3((OUTJ + NF + 255) / 256, NB), 256>>>();

    gemm_mma_kernel<1><<<dim3(8, 138), 256, SMEM_DYN>>>(out);
}

// round 15
// speedup vs baseline: 1.0693x; 1.0071x over previous
#include <cuda_runtime.h>
#include <cuda_fp16.h>
#include <cstdint>

// ---------------------------------------------------------------------------
// Problem constants
// ---------------------------------------------------------------------------
#define NB      256
#define NT      81
#define WIN     1022
#define NF      69
#define M1      (NB*NT)      // 20736 = 162*128
#define M2      (NB*NF)      // 17664 = 138*128
#define OUTJ    28550
#define XBSTR   82944        // 512*81*2
#define OBSTR   70656        // 512*69*2
#define OKSTR   138          // 69*2
#define OSTRIDE 28560        // osig row stride in halfs (57120 B, 16B-aligned)

#define KC      64           // K per chunk
#define CH      16           // 1024/64 chunks
#define TM      128
#define TN      128
#define STAGES  3

// smem per stage (bytes): A[128][72] fp16 = 18432 ; B[64][136] fp16 = 17408
#define A_STRIDEB   144      // bytes per A row (144/16=9 odd -> ldsm conflict-free)
#define B_STRIDEB   272      // bytes per B row (272/16=17 odd -> conflict-free)
#define A_OFF       0
#define B_OFF       18432
#define STAGE_BYTES 35840
#define SMEM_DYN    (STAGES*STAGE_BYTES)   // 107520 (x2 CTAs = 215040 < 228KB)
// epilogue reuse: fp32 tile 128x130x4 = 66560 <= 107520 ; half tile 128x136x2 = 34816

// ---------------------------------------------------------------------------
// Device-global scratch
// ---------------------------------------------------------------------------
__device__ __half g_binv_h[1024*1024];   // [k=2f+c][n]   (B of GEMM1)
__device__ __half g_bfwd_h[1024*1024];   // [k=n][m=2f+c] (B of GEMM2)
__device__ __half g_xhi[(size_t)M1*1024];
__device__ __half g_tf [(size_t)M1*1024];          // iSTFT frames (fp16)
__device__ __half g_osig[(size_t)NB*OSTRIDE];      // spliced signal (fp16, compact)

// ---------------------------------------------------------------------------
// PTX helpers (baseline ISA: ldmatrix + mma.sync + cp.async, sm_80+)
// ---------------------------------------------------------------------------
__device__ __forceinline__ uint32_t smem_to_u32(const void* p) {
    uint32_t a;
    asm("{ .reg .u64 t; cvta.to.shared.u64 t, %1; cvt.u32.u64 %0, t; }"
        : "=r"(a) : "l"(p));
    return a;
}
__device__ __forceinline__ void ldsm_x4(uint32_t* r, uint32_t addr) {
    asm volatile("ldmatrix.sync.aligned.m8n8.x4.shared.b16 {%0,%1,%2,%3}, [%4];"
        : "=r"(r[0]), "=r"(r[1]), "=r"(r[2]), "=r"(r[3]) : "r"(addr));
}
__device__ __forceinline__ void ldsm_x4_t(uint32_t* r, uint32_t addr) {
    asm volatile("ldmatrix.sync.aligned.m8n8.x4.trans.shared.b16 {%0,%1,%2,%3}, [%4];"
        : "=r"(r[0]), "=r"(r[1]), "=r"(r[2]), "=r"(r[3]) : "r"(addr));
}
__device__ __forceinline__ void mma16816(float* d, const uint32_t* a, const uint32_t* b) {
    asm volatile(
        "mma.sync.aligned.m16n8k16.row.col.f32.f16.f16.f32 "
        "{%0,%1,%2,%3}, {%4,%5,%6,%7}, {%8,%9}, {%0,%1,%2,%3};"
        : "+f"(d[0]), "+f"(d[1]), "+f"(d[2]), "+f"(d[3])
        : "r"(a[0]), "r"(a[1]), "r"(a[2]), "r"(a[3]), "r"(b[0]), "r"(b[1]));
}
__device__ __forceinline__ void cp16(uint32_t saddr, const void* gaddr) {
    asm volatile("cp.async.cg.shared.global [%0], [%1], 16;"
        :: "r"(saddr), "l"(gaddr));
}
#define CP_COMMIT() asm volatile("cp.async.commit_group;" ::: "memory")
#define CP_WAIT(N)  asm volatile("cp.async.wait_group %0;" :: "n"(N) : "memory")

// ---------------------------------------------------------------------------
// Prep kernels
// ---------------------------------------------------------------------------
__device__ __forceinline__ float synwin_val(int n) {
    const float c = 6.283185307179586477f / (float)WIN;
    float w = 0.5f - 0.5f * __cosf(c * (float)n);
    int d = n % 400;
    float denom = 0.f;
    #pragma unroll
    for (int j = 0; j < 3; ++j) {
        int idx = d + 400 * j;
        if (idx < WIN) {
            float wj = 0.5f - 0.5f * __cosf(c * (float)idx);
            denom += wj * wj;
        }
    }
    return w / denom;
}

// g_binv[k=2f+c][n] = synwin[n]/WIN * w_f * {cos,-sin}(2*pi*f*n/WIN); 0 for n>=1022
__global__ void fill_binv_kernel() {
    int idx = blockIdx.x * blockDim.x + threadIdx.x;   // 512*1024
    int f = idx >> 10;
    int n = idx & 1023;
    float re = 0.f, im = 0.f;
    if (n < WIN) {
        unsigned m = (unsigned)(f * n) % (unsigned)WIN;
        float ang = 6.283185307179586477f * (float)m / (float)WIN;
        float s, c;
        __sincosf(ang, &s, &c);
        float wk = (f == 0 || f == 511) ? 1.f : 2.f;
        float scale = wk * synwin_val(n) * (1.0f / (float)WIN);
        re = scale * c;
        im = -scale * s;
    }
    g_binv_h[(size_t)(2*f) * 1024 + n]   = __float2half_rn(re);
    g_binv_h[(size_t)(2*f+1) * 1024 + n] = __float2half_rn(im);
}

// g_bfwd[k=n][m=2f+c] = hann[n] * {cos,-sin}(2*pi*f*n/WIN); zero rows n>=1022
__global__ void fill_bfwd_kernel() {
    int idx = blockIdx.x * blockDim.x + threadIdx.x;   // 1024*512
    int n = idx >> 9;
    int f = idx & 511;
    float re = 0.f, im = 0.f;
    if (n < WIN) {
        const float cc = 6.283185307179586477f / (float)WIN;
        unsigned m = (unsigned)(f * n) % (unsigned)WIN;
        float ang = cc * (float)m;
        float s, c;
        __sincosf(ang, &s, &c);
        float h = 0.5f - 0.5f * __cosf(cc * (float)n);
        re = h * c;
        im = -h * s;
    }
    g_bfwd_h[(size_t)n * 1024 + 2*f]   = __float2half_rn(re);
    g_bfwd_h[(size_t)n * 1024 + 2*f+1] = __float2half_rn(im);
}

// x (B,F,T,2) -> g_xhi [(b,t)][2f+c]  -- smem tile transpose
__global__ void __launch_bounds__(256) convert_x_kernel(const float* __restrict__ x) {
    __shared__ __half2 tile[64 * 81];
    const int b  = blockIdx.y;
    const int f0 = blockIdx.x * 64;
    const float* xb = x + (size_t)b * XBSTR;
    for (int i = threadIdx.x; i < 64 * 81; i += 256) {
        int fi = i / 81, t = i - fi * 81;
        float2 v = *(const float2*)(xb + (size_t)(f0 + fi) * 162 + t * 2);
        tile[fi * 81 + t] = __floats2half2_rn(v.x, v.y);
    }
    __syncthreads();
    for (int i = threadIdx.x; i < 64 * 81; i += 256) {
        int t = i >> 6, fi = i & 63;
        *(__half2*)(g_xhi + (size_t)(b * 81 + t) * 1024 + 2 * (f0 + fi)) = tile[fi * 81 + t];
    }
}

// ---------------------------------------------------------------------------
// Fold: overlap-add + crossfade -> compact spliced signal osig (fp16).
// (All STFT A-reads are osig[f*400+n] with f<=68, n<=1023 -> index <= 28223
//  < OUTJ, so every read hits a fold-written sample; no padding needed.)
// ---------------------------------------------------------------------------
__device__ __forceinline__ float sigval(const __half* __restrict__ tfb, int s) {
    int t1 = s / 400; if (t1 > 80) t1 = 80;
    int t0 = (s >= WIN) ? (s - (WIN - 400)) / 400 : 0;
    float v = 0.f;
    for (int t = t0; t <= t1; ++t)
        v += __half2float(tfb[t * 1024 + (s - 400 * t)]);
    return v;
}

__global__ void fold_kernel() {
    int j = blockIdx.x * blockDim.x + threadIdx.x;
    int b = blockIdx.y;
    if (j >= OUTJ) return;
    int k, r;
    if (j < 1000) { k = 0; r = j; }
    else {
        int q  = (j - 1000) / 950;
        int rr = (j - 1000) - q * 950;
        k = q + 1;
        r = 50 + rr;
    }
    float cc = 1.f, dec = 0.f, inc = 0.f;
    bool xfade = (r >= 950) && (k <= 28);
    if (xfade) {
        cc  = 0.f;
        dec = (float)(1000 - r) * 0.02f;
        inc = (float)(r - 949) * 0.02f;
    }
    const __half* tfb = g_tf + (size_t)b * NT * 1024;
    float o = (cc + dec) * sigval(tfb, k * 1100 + r);
    if (xfade)
        o += inc * sigval(tfb, (k + 1) * 1100 + (r - 950));

    g_osig[(size_t)b * OSTRIDE + j] = __float2half_rn(o);
}

// ---------------------------------------------------------------------------
// fp16 tensor-core GEMM, 128x128 CTA tile, KC=64, cp.async 3-stage pipeline,
// 2 CTAs/SM. 8 warps as 2(M)x4(N); single product A*B.
// MODE 0: A=g_xhi (row stride 1024), B=g_binv_h -> g_tf (fp16)
// MODE 1: A=osig gather (row (b,f) -> b*OSTRIDE + f*400), B=g_bfwd_h -> out
// ---------------------------------------------------------------------------
template <int MODE>
__global__ void __launch_bounds__(256, 2) gemm_mma_kernel(float* __restrict__ outp) {
    extern __shared__ char smem[];
    const uint32_t sbase = smem_to_u32(smem);
    const int tid  = threadIdx.x;
    const int wid  = tid >> 5;
    const int lane = tid & 31;
    const int wm   = wid & 1;        // 2 warp rows (64 each)
    const int wn   = wid >> 1;       // 4 warp cols (32 each)
    const int n0   = blockIdx.x * TN;
    const int row0 = blockIdx.y * TM;

    const __half* Bh = (MODE == 0) ? g_binv_h : g_bfwd_h;

    float acc[4][4][4];
    #pragma unroll
    for (int i = 0; i < 4; ++i)
        #pragma unroll
        for (int j = 0; j < 4; ++j)
            #pragma unroll
            for (int q = 0; q < 4; ++q) acc[i][j][q] = 0.f;

    // Per-unit A row base pointers (gather for MODE 1), hoisted out of the loop
    const __half* arow_base[4];
    #pragma unroll
    for (int i = 0; i < 4; ++i) {
        int unit = tid + 256 * i;
        int row = unit >> 3;
        int gr = row0 + row;
        if (MODE == 0) {
            arow_base[i] = g_xhi + (size_t)gr * 1024;
        } else {
            int b = gr / NF, f = gr - b * NF;
            arow_base[i] = g_osig + (size_t)b * OSTRIDE + f * 400;
        }
    }

    auto load_chunk = [&](int c, int buf) {
        const size_t kt = (size_t)c * KC;
        const uint32_t sa = sbase + buf * STAGE_BYTES;
        // A: 128 rows x 8 segs of 16B; warp covers 4 full 128B rows per iter
        #pragma unroll
        for (int i = 0; i < 4; ++i) {
            int unit = tid + 256 * i;
            int row = unit >> 3, seg = unit & 7;
            cp16(sa + A_OFF + row * A_STRIDEB + seg * 16,
                 arow_base[i] + kt + seg * 8);
        }
        // B: 64 rows x 16 segs of 16B; warp covers 2 full 256B rows per iter
        #pragma unroll
        for (int i = 0; i < 4; ++i) {
            int unit = tid + 256 * i;
            int row = unit >> 4, seg = unit & 15;
            cp16(sa + B_OFF + row * B_STRIDEB + seg * 16,
                 Bh + (size_t)(kt + row) * 1024 + n0 + seg * 8);
        }
    };

    const uint32_t lrow = lane & 15;
    const uint32_t lsel = lane >> 4;

    #pragma unroll
    for (int s = 0; s < STAGES - 1; ++s) {
        load_chunk(s, s);
        CP_COMMIT();
    }

    for (int c = 0; c < CH; ++c) {
        CP_WAIT(STAGES - 2);
        __syncthreads();

        if (c + STAGES - 1 < CH)
            load_chunk(c + STAGES - 1, (c + STAGES - 1) % STAGES);
        CP_COMMIT();

        const int buf = c % STAGES;
        const uint32_t sb = sbase + buf * STAGE_BYTES;
        const uint32_t aB = sb + A_OFF + (wm * 64 + lrow) * A_STRIDEB + lsel * 16;
        const uint32_t bB = sb + B_OFF + lrow * B_STRIDEB + (wn * 32 + lsel * 8) * 2;

        #pragma unroll
        for (int ks = 0; ks < 4; ++ks) {
            uint32_t a[4][4];
            #pragma unroll
            for (int mt = 0; mt < 4; ++mt)
                ldsm_x4(a[mt], aB + mt * 16 * A_STRIDEB + ks * 32);
            uint32_t b[2][4];
            const uint32_t pb = bB + ks * 16 * B_STRIDEB;
            #pragma unroll
            for (int bt = 0; bt < 2; ++bt)
                ldsm_x4_t(b[bt], pb + bt * 32);
            #pragma unroll
            for (int mt = 0; mt < 4; ++mt)
                #pragma unroll
                for (int nt = 0; nt < 4; ++nt)
                    mma16816(acc[mt][nt], a[mt], &b[nt >> 1][(nt & 1) * 2]);
        }
    }

    // ---- epilogue: stage to smem, then coalesced global stores ----
    __syncthreads();   // all warps done reading pipeline smem

    if (MODE == 0) {
        __half* tileh = (__half*)smem;                // [128][136] halfs
        #pragma unroll
        for (int mt = 0; mt < 4; ++mt) {
            #pragma unroll
            for (int half = 0; half < 2; ++half) {
                const int r = wm * 64 + mt * 16 + (lane >> 2) + half * 8;
                #pragma unroll
                for (int nt = 0; nt < 4; ++nt) {
                    const int col = wn * 32 + nt * 8 + (lane & 3) * 2;
                    *(__half2*)(tileh + r * 136 + col) =
                        __floats2half2_rn(acc[mt][nt][half * 2], acc[mt][nt][half * 2 + 1]);
                }
            }
        }
        __syncthreads();
        #pragma unroll
        for (int u = tid; u < 128 * 16; u += 256) {
            int r = u >> 4, s = u & 15;
            *(uint4*)(g_tf + (size_t)(row0 + r) * 1024 + n0 + s * 8) =
                *(const uint4*)(tileh + r * 136 + s * 8);
        }
    } else {
        float* tilef = (float*)smem;                  // [128][130] floats
        #pragma unroll
        for (int mt = 0; mt < 4; ++mt) {
            #pragma unroll
            for (int half = 0; half < 2; ++half) {
                const int r = wm * 64 + mt * 16 + (lane >> 2) + half * 8;
                #pragma unroll
                for (int nt = 0; nt < 4; ++nt) {
                    const int col = wn * 32 + nt * 8 + (lane & 3) * 2;
                    tilef[r * 130 + col]     = acc[mt][nt][half * 2];
                    tilef[r * 130 + col + 1] = acc[mt][nt][half * 2 + 1];
                }
            }
        }
        __syncthreads();
        const int k0 = n0 >> 1;
        #pragma unroll 4
        for (int i = tid; i < 128 * 128; i += 256) {
            int k16 = i >> 8, j = i & 255;
            int r = j >> 1, c = j & 1;
            int gr = row0 + r;
            int b = gr / NF, f = gr - b * NF;
            outp[(size_t)b * OBSTR + (k0 + k16) * OKSTR + f * 2 + c] =
                tilef[r * 130 + k16 * 2 + c];
        }
    }
}

// ---------------------------------------------------------------------------
// Launch (6 launches)
// ---------------------------------------------------------------------------
extern "C" void kernel_launch(void* const* d_in, const int* in_sizes, int n_in,
                              void* d_out, int out_size) {
    const float* x = (const float*)d_in[0];
    float* out = (float*)d_out;

    cudaFuncSetAttribute((const void*)gemm_mma_kernel<0>,
                         cudaFuncAttributeMaxDynamicSharedMemorySize, SMEM_DYN);
    cudaFuncSetAttribute((const void*)gemm_mma_kernel<1>,
                         cudaFuncAttributeMaxDynamicSharedMemorySize, SMEM_DYN);

    convert_x_kernel<<<dim3(8, NB), 256>>>(x);
    fill_binv_kernel<<<2048, 256>>>();

    gemm_mma_kernel<0><<<dim3(8, 162), 256, SMEM_DYN>>>(nullptr);

    fill_bfwd_kernel<<<2048, 256>>>();
    fold_kernel<<<dim3((OUTJ + 255) / 256, NB), 256>>>();

    gemm_mma_kernel<1><<<dim3(8, 138), 256, SMEM_DYN>>>(out);
}

// round 16
// speedup vs baseline: 1.0967x; 1.0257x over previous
#include <cuda_runtime.h>
#include <cuda_fp16.h>
#include <cstdint>

// ---------------------------------------------------------------------------
// Problem constants
// ---------------------------------------------------------------------------
#define NB      256
#define NT      81
#define WIN     1022
#define NF      69
#define M1      (NB*NT)      // 20736 = 162*128
#define M2      (NB*NF)      // 17664 = 138*128
#define OUTJ    28550
#define XBSTR   82944        // 512*81*2
#define OBSTR   70656        // 512*69*2
#define OKSTR   138          // 69*2
#define OSTRIDE 28560        // osig row stride in halfs (57120 B, 16B-aligned)

#define KC      64           // K per chunk
#define CH      16           // 1024/64 chunks
#define TM      128
#define TN      128
#define STAGES  3

// smem per stage (bytes): A[128][72] fp16 = 18432 ; B[64][136] fp16 = 17408
#define A_STRIDEB   144
#define B_STRIDEB   272
#define A_OFF       0
#define B_OFF       18432
#define STAGE_BYTES 35840
#define SMEM_DYN    (STAGES*STAGE_BYTES)   // 107520 (x2 CTAs = 215040 < 228KB)

// ---------------------------------------------------------------------------
// Device-global scratch
// ---------------------------------------------------------------------------
__device__ __half g_binv_h[1024*1024];   // [k=2f+c][n]   (B of GEMM1)
__device__ __half g_bfwd_h[1024*1024];   // [k=n][m=2f+c] (B of GEMM2)
__device__ __half g_xhi[(size_t)M1*1024];
__device__ __half g_tf [(size_t)M1*1024];          // iSTFT frames (fp16)
__device__ __half g_osig[(size_t)NB*OSTRIDE];      // spliced signal (fp16)

// ---------------------------------------------------------------------------
// PTX helpers
// ---------------------------------------------------------------------------
__device__ __forceinline__ uint32_t smem_to_u32(const void* p) {
    uint32_t a;
    asm("{ .reg .u64 t; cvta.to.shared.u64 t, %1; cvt.u32.u64 %0, t; }"
        : "=r"(a) : "l"(p));
    return a;
}
__device__ __forceinline__ void ldsm_x4(uint32_t* r, uint32_t addr) {
    asm volatile("ldmatrix.sync.aligned.m8n8.x4.shared.b16 {%0,%1,%2,%3}, [%4];"
        : "=r"(r[0]), "=r"(r[1]), "=r"(r[2]), "=r"(r[3]) : "r"(addr));
}
__device__ __forceinline__ void ldsm_x4_t(uint32_t* r, uint32_t addr) {
    asm volatile("ldmatrix.sync.aligned.m8n8.x4.trans.shared.b16 {%0,%1,%2,%3}, [%4];"
        : "=r"(r[0]), "=r"(r[1]), "=r"(r[2]), "=r"(r[3]) : "r"(addr));
}
__device__ __forceinline__ void mma16816(float* d, const uint32_t* a, const uint32_t* b) {
    asm volatile(
        "mma.sync.aligned.m16n8k16.row.col.f32.f16.f16.f32 "
        "{%0,%1,%2,%3}, {%4,%5,%6,%7}, {%8,%9}, {%0,%1,%2,%3};"
        : "+f"(d[0]), "+f"(d[1]), "+f"(d[2]), "+f"(d[3])
        : "r"(a[0]), "r"(a[1]), "r"(a[2]), "r"(a[3]), "r"(b[0]), "r"(b[1]));
}
__device__ __forceinline__ void cp16(uint32_t saddr, const void* gaddr) {
    asm volatile("cp.async.cg.shared.global [%0], [%1], 16;"
        :: "r"(saddr), "l"(gaddr));
}
#define CP_COMMIT() asm volatile("cp.async.commit_group;" ::: "memory")
#define CP_WAIT(N)  asm volatile("cp.async.wait_group %0;" :: "n"(N) : "memory")

// ---------------------------------------------------------------------------
// Merged prep kernel: sections [0,2048) convert_x, [2048,4096) fill_binv,
// [4096,6144) fill_bfwd. All independent.
// ---------------------------------------------------------------------------
__device__ __forceinline__ float synwin_val(int n) {
    const float c = 6.283185307179586477f / (float)WIN;
    float w = 0.5f - 0.5f * __cosf(c * (float)n);
    int d = n % 400;
    float denom = 0.f;
    #pragma unroll
    for (int j = 0; j < 3; ++j) {
        int idx = d + 400 * j;
        if (idx < WIN) {
            float wj = 0.5f - 0.5f * __cosf(c * (float)idx);
            denom += wj * wj;
        }
    }
    return w / denom;
}

__global__ void __launch_bounds__(256) prep_kernel(const float* __restrict__ x) {
    __shared__ __half2 tile[64 * 81];
    const int bx  = blockIdx.x;
    const int tid = threadIdx.x;

    if (bx < 2048) {
        // ---- convert_x: x (B,F,T,2) -> g_xhi [(b,t)][2f+c] ----
        const int b  = bx >> 3;
        const int f0 = (bx & 7) * 64;
        const float* xb = x + (size_t)b * XBSTR;
        for (int i = tid; i < 64 * 81; i += 256) {
            int fi = i / 81, t = i - fi * 81;
            float2 v = *(const float2*)(xb + (size_t)(f0 + fi) * 162 + t * 2);
            tile[fi * 81 + t] = __floats2half2_rn(v.x, v.y);
        }
        __syncthreads();
        for (int i = tid; i < 64 * 81; i += 256) {
            int t = i >> 6, fi = i & 63;
            *(__half2*)(g_xhi + (size_t)(b * 81 + t) * 1024 + 2 * (f0 + fi)) = tile[fi * 81 + t];
        }
    } else if (bx < 4096) {
        // ---- fill_binv: [k=2f+c][n]; 0 for n >= 1022 ----
        int idx = (bx - 2048) * 256 + tid;     // 512*1024
        int f = idx >> 10;
        int n = idx & 1023;
        float re = 0.f, im = 0.f;
        if (n < WIN) {
            unsigned m = (unsigned)(f * n) % (unsigned)WIN;
            float ang = 6.283185307179586477f * (float)m / (float)WIN;
            float s, c;
            __sincosf(ang, &s, &c);
            float wk = (f == 0 || f == 511) ? 1.f : 2.f;
            float scale = wk * synwin_val(n) * (1.0f / (float)WIN);
            re = scale * c;
            im = -scale * s;
        }
        g_binv_h[(size_t)(2*f) * 1024 + n]   = __float2half_rn(re);
        g_binv_h[(size_t)(2*f+1) * 1024 + n] = __float2half_rn(im);
    } else {
        // ---- fill_bfwd: [k=n][m=2f+c]; zero rows n >= 1022 ----
        int idx = (bx - 4096) * 256 + tid;     // 1024*512
        int n = idx >> 9;
        int f = idx & 511;
        float re = 0.f, im = 0.f;
        if (n < WIN) {
            const float cc = 6.283185307179586477f / (float)WIN;
            unsigned m = (unsigned)(f * n) % (unsigned)WIN;
            float ang = cc * (float)m;
            float s, c;
            __sincosf(ang, &s, &c);
            float h = 0.5f - 0.5f * __cosf(cc * (float)n);
            re = h * c;
            im = -h * s;
        }
        g_bfwd_h[(size_t)n * 1024 + 2*f]   = __float2half_rn(re);
        g_bfwd_h[(size_t)n * 1024 + 2*f+1] = __float2half_rn(im);
    }
}

// ---------------------------------------------------------------------------
// Fold: overlap-add + crossfade -> compact spliced signal osig (fp16).
// ---------------------------------------------------------------------------
__device__ __forceinline__ float sigval(const __half* __restrict__ tfb, int s) {
    int t1 = s / 400; if (t1 > 80) t1 = 80;
    int t0 = (s >= WIN) ? (s - (WIN - 400)) / 400 : 0;
    float v = 0.f;
    for (int t = t0; t <= t1; ++t)
        v += __half2float(tfb[t * 1024 + (s - 400 * t)]);
    return v;
}

__global__ void fold_kernel() {
    int j = blockIdx.x * blockDim.x + threadIdx.x;
    int b = blockIdx.y;
    if (j >= OUTJ) return;
    int k, r;
    if (j < 1000) { k = 0; r = j; }
    else {
        int q  = (j - 1000) / 950;
        int rr = (j - 1000) - q * 950;
        k = q + 1;
        r = 50 + rr;
    }
    float cc = 1.f, dec = 0.f, inc = 0.f;
    bool xfade = (r >= 950) && (k <= 28);
    if (xfade) {
        cc  = 0.f;
        dec = (float)(1000 - r) * 0.02f;
        inc = (float)(r - 949) * 0.02f;
    }
    const __half* tfb = g_tf + (size_t)b * NT * 1024;
    float o = (cc + dec) * sigval(tfb, k * 1100 + r);
    if (xfade)
        o += inc * sigval(tfb, (k + 1) * 1100 + (r - 950));

    g_osig[(size_t)b * OSTRIDE + j] = __float2half_rn(o);
}

// ---------------------------------------------------------------------------
// fp16 tensor-core GEMM, 128x128 CTA tile, KC=64, cp.async 3-stage pipeline,
// 2 CTAs/SM. Reordered mainloop: sync -> load(c+2) -> commit -> wait -> consume.
// MODE 0: A=g_xhi, B=g_binv_h -> g_tf (fp16)
// MODE 1: A=osig gather (row (b,f)), B=g_bfwd_h -> out (fp32)
// ---------------------------------------------------------------------------
template <int MODE>
__global__ void __launch_bounds__(256, 2) gemm_mma_kernel(float* __restrict__ outp) {
    extern __shared__ char smem[];
    const uint32_t sbase = smem_to_u32(smem);
    const int tid  = threadIdx.x;
    const int wid  = tid >> 5;
    const int lane = tid & 31;
    const int wm   = wid & 1;
    const int wn   = wid >> 1;
    const int n0   = blockIdx.x * TN;
    const int row0 = blockIdx.y * TM;

    const __half* Bh = (MODE == 0) ? g_binv_h : g_bfwd_h;

    float acc[4][4][4];
    #pragma unroll
    for (int i = 0; i < 4; ++i)
        #pragma unroll
        for (int j = 0; j < 4; ++j)
            #pragma unroll
            for (int q = 0; q < 4; ++q) acc[i][j][q] = 0.f;

    const __half* arow_base[4];
    #pragma unroll
    for (int i = 0; i < 4; ++i) {
        int unit = tid + 256 * i;
        int row = unit >> 3;
        int gr = row0 + row;
        if (MODE == 0) {
            arow_base[i] = g_xhi + (size_t)gr * 1024;
        } else {
            int b = gr / NF, f = gr - b * NF;
            arow_base[i] = g_osig + (size_t)b * OSTRIDE + f * 400;
        }
    }

    auto load_chunk = [&](int c, int buf) {
        const size_t kt = (size_t)c * KC;
        const uint32_t sa = sbase + buf * STAGE_BYTES;
        #pragma unroll
        for (int i = 0; i < 4; ++i) {
            int unit = tid + 256 * i;
            int row = unit >> 3, seg = unit & 7;
            cp16(sa + A_OFF + row * A_STRIDEB + seg * 16,
                 arow_base[i] + kt + seg * 8);
        }
        #pragma unroll
        for (int i = 0; i < 4; ++i) {
            int unit = tid + 256 * i;
            int row = unit >> 4, seg = unit & 15;
            cp16(sa + B_OFF + row * B_STRIDEB + seg * 16,
                 Bh + (size_t)(kt + row) * 1024 + n0 + seg * 8);
        }
    };

    const uint32_t lrow = lane & 15;
    const uint32_t lsel = lane >> 4;

    #pragma unroll
    for (int s = 0; s < STAGES - 1; ++s) {
        load_chunk(s, s);
        CP_COMMIT();
    }

    for (int c = 0; c < CH; ++c) {
        // sync first (protects buffer (c+2)%3, read at iter c-1), then issue
        // loads while chunk c's cp.async is still in flight.
        __syncthreads();
        if (c + STAGES - 1 < CH) {
            load_chunk(c + STAGES - 1, (c + STAGES - 1) % STAGES);
            CP_COMMIT();
            CP_WAIT(STAGES - 1);   // <=2 pending: waits exactly for chunk c
        } else {
            CP_WAIT(0);            // tail: drain everything
        }

        const int buf = c % STAGES;
        const uint32_t sb = sbase + buf * STAGE_BYTES;
        const uint32_t aB = sb + A_OFF + (wm * 64 + lrow) * A_STRIDEB + lsel * 16;
        const uint32_t bB = sb + B_OFF + lrow * B_STRIDEB + (wn * 32 + lsel * 8) * 2;

        #pragma unroll
        for (int ks = 0; ks < 4; ++ks) {
            uint32_t a[4][4];
            #pragma unroll
            for (int mt = 0; mt < 4; ++mt)
                ldsm_x4(a[mt], aB + mt * 16 * A_STRIDEB + ks * 32);
            uint32_t b[2][4];
            const uint32_t pb = bB + ks * 16 * B_STRIDEB;
            #pragma unroll
            for (int bt = 0; bt < 2; ++bt)
                ldsm_x4_t(b[bt], pb + bt * 32);
            #pragma unroll
            for (int mt = 0; mt < 4; ++mt)
                #pragma unroll
                for (int nt = 0; nt < 4; ++nt)
                    mma16816(acc[mt][nt], a[mt], &b[nt >> 1][(nt & 1) * 2]);
        }
    }

    // ---- epilogue: stage to smem, then coalesced global stores ----
    __syncthreads();

    if (MODE == 0) {
        __half* tileh = (__half*)smem;                // [128][136] halfs
        #pragma unroll
        for (int mt = 0; mt < 4; ++mt) {
            #pragma unroll
            for (int half = 0; half < 2; ++half) {
                const int r = wm * 64 + mt * 16 + (lane >> 2) + half * 8;
                #pragma unroll
                for (int nt = 0; nt < 4; ++nt) {
                    const int col = wn * 32 + nt * 8 + (lane & 3) * 2;
                    *(__half2*)(tileh + r * 136 + col) =
                        __floats2half2_rn(acc[mt][nt][half * 2], acc[mt][nt][half * 2 + 1]);
                }
            }
        }
        __syncthreads();
        #pragma unroll
        for (int u = tid; u < 128 * 16; u += 256) {
            int r = u >> 4, s = u & 15;
            *(uint4*)(g_tf + (size_t)(row0 + r) * 1024 + n0 + s * 8) =
                *(const uint4*)(tileh + r * 136 + s * 8);
        }
    } else {
        float* tilef = (float*)smem;                  // [128][130] floats
        #pragma unroll
        for (int mt = 0; mt < 4; ++mt) {
            #pragma unroll
            for (int half = 0; half < 2; ++half) {
                const int r = wm * 64 + mt * 16 + (lane >> 2) + half * 8;
                #pragma unroll
                for (int nt = 0; nt < 4; ++nt) {
                    const int col = wn * 32 + nt * 8 + (lane & 3) * 2;
                    tilef[r * 130 + col]     = acc[mt][nt][half * 2];
                    tilef[r * 130 + col + 1] = acc[mt][nt][half * 2 + 1];
                }
            }
        }
        __syncthreads();
        const int k0 = n0 >> 1;
        #pragma unroll 4
        for (int i = tid; i < 128 * 128; i += 256) {
            int k16 = i >> 8, j = i & 255;
            int r = j >> 1, c = j & 1;
            int gr = row0 + r;
            int b = gr / NF, f = gr - b * NF;
            outp[(size_t)b * OBSTR + (k0 + k16) * OKSTR + f * 2 + c] =
                tilef[r * 130 + k16 * 2 + c];
        }
    }
}

// ---------------------------------------------------------------------------
// Launch (4 launches)
// ---------------------------------------------------------------------------
extern "C" void kernel_launch(void* const* d_in, const int* in_sizes, int n_in,
                              void* d_out, int out_size) {
    const float* x = (const float*)d_in[0];
    float* out = (float*)d_out;

    cudaFuncSetAttribute((const void*)gemm_mma_kernel<0>,
                         cudaFuncAttributeMaxDynamicSharedMemorySize, SMEM_DYN);
    cudaFuncSetAttribute((const void*)gemm_mma_kernel<1>,
                         cudaFuncAttributeMaxDynamicSharedMemorySize, SMEM_DYN);

    prep_kernel<<<6144, 256>>>(x);

    gemm_mma_kernel<0><<<dim3(8, 162), 256, SMEM_DYN>>>(nullptr);

    fold_kernel<<<dim3((OUTJ + 255) / 256, NB), 256>>>();

    gemm_mma_kernel<1><<<dim3(8, 138), 256, SMEM_DYN>>>(out);
}